// round 7
// baseline (speedup 1.0000x reference)
#include <cuda_runtime.h>
#include <cuda_bf16.h>
#include <stdint.h>

// Problem constants
#define B_N 4
#define S_N 2048
#define D_N 1024
#define H_N 16
#define DK_N 64

#define HEAD_EL (8192u * 1024u)        // B*H*S*DK == M*D
#define IN_EL   (3u * HEAD_EL)
#define W_EL    (4u * 1024u * 1024u)

// bf16 hi/lo scratch (allocation-free: static device globals)
__device__ __nv_bfloat16 g_inh[IN_EL], g_inl[IN_EL];
__device__ __nv_bfloat16 g_wh[W_EL],  g_wl[W_EL];
__device__ __nv_bfloat16 g_qh[HEAD_EL], g_ql[HEAD_EL];
__device__ __nv_bfloat16 g_kh[HEAD_EL], g_kl[HEAD_EL];
__device__ __nv_bfloat16 g_vh[HEAD_EL], g_vl[HEAD_EL];
__device__ __nv_bfloat16 g_ch[HEAD_EL], g_cl[HEAD_EL];

// ===========================================================================
// Helpers (compute_103-portable: ldmatrix / mma.sync / cp.async)
// ===========================================================================
__device__ __forceinline__ uint32_t smem_u32(const void* p) {
    uint32_t a;
    asm("{ .reg .u64 t; cvta.to.shared.u64 t, %1; cvt.u32.u64 %0, t; }"
        : "=r"(a) : "l"(p));
    return a;
}
__device__ __forceinline__ void ldsm_x4(uint32_t* r, uint32_t addr) {
    asm volatile("ldmatrix.sync.aligned.m8n8.x4.shared.b16 {%0,%1,%2,%3}, [%4];"
        : "=r"(r[0]), "=r"(r[1]), "=r"(r[2]), "=r"(r[3]) : "r"(addr));
}
__device__ __forceinline__ void ldsm_x4t(uint32_t* r, uint32_t addr) {
    asm volatile("ldmatrix.sync.aligned.m8n8.x4.trans.shared.b16 {%0,%1,%2,%3}, [%4];"
        : "=r"(r[0]), "=r"(r[1]), "=r"(r[2]), "=r"(r[3]) : "r"(addr));
}
__device__ __forceinline__ void mma16816(float* d, const uint32_t* a, const uint32_t* b) {
    asm volatile(
        "mma.sync.aligned.m16n8k16.row.col.f32.bf16.bf16.f32 "
        "{%0,%1,%2,%3}, {%4,%5,%6,%7}, {%8,%9}, {%0,%1,%2,%3};"
        : "+f"(d[0]), "+f"(d[1]), "+f"(d[2]), "+f"(d[3])
        : "r"(a[0]), "r"(a[1]), "r"(a[2]), "r"(a[3]), "r"(b[0]), "r"(b[1]));
}
__device__ __forceinline__ void bf16split2(float x, float y, uint32_t& hi, uint32_t& lo) {
    union { __nv_bfloat162 b; uint32_t u; } h, l;
    h.b = __floats2bfloat162_rn(x, y);
    l.b = __floats2bfloat162_rn(x - __low2float(h.b), y - __high2float(h.b));
    hi = h.u; lo = l.u;
}
__device__ __forceinline__ void cpa16(uint32_t s, const void* g) {
    asm volatile("cp.async.cg.shared.global [%0], [%1], 16;" :: "r"(s), "l"(g));
}
#define CP_COMMIT() asm volatile("cp.async.commit_group;" ::: "memory")
#define CP_WAIT(n)  asm volatile("cp.async.wait_group %0;" :: "n"(n) : "memory")

// ===========================================================================
// Pre-pass: fp32 -> bf16 hi/lo (fused: 3 inputs / 4 weights per launch)
// ===========================================================================
__global__ __launch_bounds__(256) void convert_in(
    const float* __restrict__ q, const float* __restrict__ k,
    const float* __restrict__ v)
{
    const int z = blockIdx.z;
    const float* src = (z == 0) ? q : (z == 1) ? k : v;
    __nv_bfloat16* dh = g_inh + (size_t)z * HEAD_EL;
    __nv_bfloat16* dl = g_inl + (size_t)z * HEAD_EL;
    const int i = blockIdx.x * 256 + threadIdx.x;
    const float4 val = ((const float4*)src)[i];
    uint32_t h0, l0, h1, l1;
    bf16split2(val.x, val.y, h0, l0);
    bf16split2(val.z, val.w, h1, l1);
    ((uint2*)dh)[i] = make_uint2(h0, h1);
    ((uint2*)dl)[i] = make_uint2(l0, l1);
}

__global__ __launch_bounds__(256) void convert_w(
    const float* __restrict__ wq, const float* __restrict__ wk,
    const float* __restrict__ wv, const float* __restrict__ wo)
{
    const int z = blockIdx.z;
    const float* src = (z == 0) ? wq : (z == 1) ? wk : (z == 2) ? wv : wo;
    __nv_bfloat16* dh = g_wh + (size_t)z * 1024 * 1024;
    __nv_bfloat16* dl = g_wl + (size_t)z * 1024 * 1024;
    const int i = blockIdx.x * 256 + threadIdx.x;
    const float4 val = ((const float4*)src)[i];
    uint32_t h0, l0, h1, l1;
    bf16split2(val.x, val.y, h0, l0);
    bf16split2(val.z, val.w, h1, l1);
    ((uint2*)dh)[i] = make_uint2(h0, h1);
    ((uint2*)dl)[i] = make_uint2(l0, l1);
}

// ===========================================================================
// GEMM: D = A @ W^T (+bias). CTA 128(M) x 256(N), BK=32, 8 warps (2m x 4n),
// warp tile 64x64, 3-stage cp.async pipeline, combined hi/lo x4 for B.
// Stage: Ah(10240) Al(10240) Bh(20480) Bl(20480) = 61440 B, 80 B row stride.
// ===========================================================================
#define G_AH 0
#define G_AL 10240
#define G_BH 20480
#define G_BDL 20480             // Bl - Bh
#define G_STAGE 61440
#define SMEM_GEMM (3 * G_STAGE)

__device__ __forceinline__ void gemm_stage_issue(
    uint32_t st, const __nv_bfloat16* __restrict__ Ah,
    const __nv_bfloat16* __restrict__ Al, const __nv_bfloat16* __restrict__ Wh,
    const __nv_bfloat16* __restrict__ Wl, int kt, int tid)
{
    #pragma unroll
    for (int i = 0; i < 2; ++i) {         // A: 128 rows x 4 chunks, hi+lo
        const int c = tid + i * 256;
        const int row = c >> 2, ch = c & 3;
        const uint32_t d = st + row * 80 + ch * 16;
        const size_t s = (size_t)row * 1024 + kt * 32 + ch * 8;
        cpa16(d + G_AH, Ah + s);
        cpa16(d + G_AL, Al + s);
    }
    #pragma unroll
    for (int i = 0; i < 4; ++i) {         // B: 256 rows x 4 chunks, hi+lo
        const int c = tid + i * 256;
        const int row = c >> 2, ch = c & 3;
        const uint32_t d = st + G_BH + row * 80 + ch * 16;
        const size_t s = (size_t)row * 1024 + kt * 32 + ch * 8;
        cpa16(d, Wh + s);
        cpa16(d + G_BDL, Wl + s);
    }
}

template <int MODE>
__device__ __forceinline__ void gemm_bf_body(
    const __nv_bfloat16* __restrict__ Ah, const __nv_bfloat16* __restrict__ Al,
    const __nv_bfloat16* __restrict__ Wh, const __nv_bfloat16* __restrict__ Wl,
    const float* __restrict__ bias, float scale,
    float* __restrict__ outf,
    __nv_bfloat16* __restrict__ outh, __nv_bfloat16* __restrict__ outl,
    int bm, int bn)
{
    extern __shared__ char smg[];
    const uint32_t sb = smem_u32(smg);
    const int tid = threadIdx.x;
    const int lane = tid & 31;
    const int w = tid >> 5;
    const int wm = w >> 2;              // 0..1 -> rows wm*64
    const int wn = w & 3;               // 0..3 -> cols wn*64

    const __nv_bfloat16* Agh = Ah + (size_t)bm * 128 * 1024;
    const __nv_bfloat16* Agl = Al + (size_t)bm * 128 * 1024;
    const __nv_bfloat16* Wgh = Wh + (size_t)bn * 256 * 1024;
    const __nv_bfloat16* Wgl = Wl + (size_t)bn * 256 * 1024;

    gemm_stage_issue(sb,               Agh, Agl, Wgh, Wgl, 0, tid); CP_COMMIT();
    gemm_stage_issue(sb + G_STAGE,     Agh, Agl, Wgh, Wgl, 1, tid); CP_COMMIT();
    gemm_stage_issue(sb + 2 * G_STAGE, Agh, Agl, Wgh, Wgl, 2, tid); CP_COMMIT();

    float d[4][8][4];
    #pragma unroll
    for (int mi = 0; mi < 4; ++mi)
        #pragma unroll
        for (int ni = 0; ni < 8; ++ni)
            #pragma unroll
            for (int q = 0; q < 4; ++q) d[mi][ni][q] = 0.0f;

    const int arow = wm * 64 + (lane & 15);
    const int akoff = (lane >> 4) << 3;
    const int brow = wn * 64 + (lane & 7);
    const int bkoff = ((lane >> 3) & 1) << 3;
    const uint32_t losel = (lane & 16) ? G_BDL : 0;

    for (int kt = 0; kt < 32; ++kt) {
        if (kt < 30) { CP_WAIT(2); } else if (kt == 30) { CP_WAIT(1); } else { CP_WAIT(0); }
        __syncthreads();
        const uint32_t st = sb + (uint32_t)(kt % 3) * G_STAGE;
        #pragma unroll
        for (int kk = 0; kk < 32; kk += 16) {
            uint32_t ah[4][4], al[4][4];
            #pragma unroll
            for (int mi = 0; mi < 4; ++mi) {
                const uint32_t ao = st + (arow + mi * 16) * 80 + (kk + akoff) * 2;
                ldsm_x4(ah[mi], ao + G_AH);
                ldsm_x4(al[mi], ao + G_AL);
            }
            #pragma unroll
            for (int ni = 0; ni < 8; ++ni) {
                uint32_t bb[4];   // bb[0..1]=hi, bb[2..3]=lo (combined x4)
                const uint32_t bo = st + G_BH + losel + (brow + ni * 8) * 80 + (kk + bkoff) * 2;
                ldsm_x4(bb, bo);
                #pragma unroll
                for (int mi = 0; mi < 4; ++mi) {
                    mma16816(d[mi][ni], ah[mi], bb);
                    mma16816(d[mi][ni], ah[mi], bb + 2);
                    mma16816(d[mi][ni], al[mi], bb);
                }
            }
        }
        __syncthreads();
        if (kt + 3 < 32) {
            gemm_stage_issue(sb + (uint32_t)(kt % 3) * G_STAGE, Agh, Agl, Wgh, Wgl, kt + 3, tid);
            CP_COMMIT();
        }
    }

    // epilogue
    const int r_base = bm * 128 + wm * 64 + (lane >> 2);
    const int c_base = bn * 256 + wn * 64 + 2 * (lane & 3);
    #pragma unroll
    for (int mi = 0; mi < 4; ++mi)
        #pragma unroll
        for (int ni = 0; ni < 8; ++ni) {
            const int col = c_base + ni * 8;
            const float b0 = bias[col], b1 = bias[col + 1];
            #pragma unroll
            for (int rr = 0; rr < 2; ++rr) {
                const int row = r_base + mi * 16 + rr * 8;
                const float vx = (d[mi][ni][rr * 2 + 0] + b0) * scale;
                const float vy = (d[mi][ni][rr * 2 + 1] + b1) * scale;
                if (MODE == 1) {
                    const int bb = row >> 11;
                    const int s = row & (S_N - 1);
                    const int hh = col >> 6;
                    const int dk = col & 63;
                    const size_t idx = (((size_t)(bb * H_N + hh) * S_N + s) * DK_N) + dk;
                    uint32_t h, l;
                    bf16split2(vx, vy, h, l);
                    *(uint32_t*)(outh + idx) = h;
                    *(uint32_t*)(outl + idx) = l;
                } else {
                    float2 v; v.x = vx; v.y = vy;
                    *(float2*)(outf + (size_t)row * D_N + col) = v;
                }
            }
        }
}

__global__ __launch_bounds__(256) void qkv_proj_mma(
    const float* __restrict__ bq, const float* __restrict__ bk,
    const float* __restrict__ bv)
{
    const int z = blockIdx.z;
    const float* bias = (z == 0) ? bq : (z == 1) ? bk : bv;
    __nv_bfloat16* oh = (z == 0) ? g_qh : (z == 1) ? g_kh : g_vh;
    __nv_bfloat16* ol = (z == 0) ? g_ql : (z == 1) ? g_kl : g_vl;
    const float scale = (z == 0) ? 0.125f : 1.0f;
    gemm_bf_body<1>(g_inh + (size_t)z * HEAD_EL, g_inl + (size_t)z * HEAD_EL,
                    g_wh + (size_t)z * 1024 * 1024, g_wl + (size_t)z * 1024 * 1024,
                    bias, scale, nullptr, oh, ol, blockIdx.y, blockIdx.x);
}

__global__ __launch_bounds__(256) void oproj_mma(
    const float* __restrict__ bo, float* __restrict__ out)
{
    gemm_bf_body<0>(g_ch, g_cl,
                    g_wh + (size_t)3 * 1024 * 1024, g_wl + (size_t)3 * 1024 * 1024,
                    bo, 1.0f, out, nullptr, nullptr, blockIdx.y, blockIdx.x);
}

// ===========================================================================
// Flash attention: CTA = one (b,h) x 256 q-rows, 8 warps x 32 rows,
// key tiles of 64, 3-stage cp.async KV pipeline, online softmax.
// Q smem persistent (hi/lo, re-LDSM per chunk -> low regs).
// Stage: Kh(9216) Kl(9216) Vh(9216) Vl(9216) = 36864 B, 144 B row stride.
// ===========================================================================
#define FQ_L 36864               // Q lo offset (Q comp = 256*144)
#define F_ST0 73728
#define F_KDL 9216               // Kl - Kh (also Vl - Vh)
#define F_VH 18432
#define F_STAGE 36864
#define F_MS (F_ST0 + 3 * F_STAGE)     // 184320
#define SMEM_FLASH (F_MS + 8192)       // 192512

__device__ __forceinline__ void kv_stage_issue(
    uint32_t st, const __nv_bfloat16* __restrict__ kh,
    const __nv_bfloat16* __restrict__ kl, const __nv_bfloat16* __restrict__ vh,
    const __nv_bfloat16* __restrict__ vl, int t, int tid)
{
    #pragma unroll
    for (int i = 0; i < 8; ++i) {
        const int comp = i >> 1;                // 0..3 = Kh,Kl,Vh,Vl
        const int c = (tid + (i & 1) * 256) & 511;  // 0..511
        const int row = c >> 3, ch = c & 7;
        const uint32_t d = st + comp * 9216 + row * 144 + ch * 16;
        const __nv_bfloat16* src =
            (comp == 0 ? kh : comp == 1 ? kl : comp == 2 ? vh : vl)
            + ((size_t)t * 64 + row) * 64 + ch * 8;
        cpa16(d, src);
    }
}

__global__ __launch_bounds__(256)
void flash_mma(const int* __restrict__ mask)
{
    extern __shared__ char smf[];
    const uint32_t sb = smem_u32(smf);
    const int tid = threadIdx.x;
    const int lane = tid & 31;
    const int w = tid >> 5;
    const int bh = blockIdx.y;
    const int q0 = blockIdx.x * 256;
    const int b = bh >> 4;
    const int h = bh & 15;

    const size_t hoff = (size_t)bh * S_N * DK_N;
    const __nv_bfloat16* Qh = g_qh + hoff + (size_t)q0 * DK_N;
    const __nv_bfloat16* Ql = g_ql + hoff + (size_t)q0 * DK_N;
    const __nv_bfloat16* Kh = g_kh + hoff;
    const __nv_bfloat16* Kl = g_kl + hoff;
    const __nv_bfloat16* Vh = g_vh + hoff;
    const __nv_bfloat16* Vl = g_vl + hoff;
    const int* mg = mask + b * S_N;

    // prologue: Q (hi/lo) + mask (group A), then KV stages 0,1,2
    #pragma unroll
    for (int i = 0; i < 8; ++i) {
        const int c = tid + i * 256;            // 0..2047
        const int row = c >> 3, ch = c & 7;
        const uint32_t d = sb + row * 144 + ch * 16;
        const size_t s = (size_t)row * 64 + ch * 8;
        cpa16(d, Qh + s);
        cpa16(d + FQ_L, Ql + s);
    }
    #pragma unroll
    for (int i = 0; i < 2; ++i) {
        const int c = tid + i * 256;            // 512 chunks of 16B
        cpa16(sb + F_MS + c * 16, mg + c * 4);
    }
    CP_COMMIT();
    kv_stage_issue(sb + F_ST0,               Kh, Kl, Vh, Vl, 0, tid); CP_COMMIT();
    kv_stage_issue(sb + F_ST0 + F_STAGE,     Kh, Kl, Vh, Vl, 1, tid); CP_COMMIT();
    kv_stage_issue(sb + F_ST0 + 2 * F_STAGE, Kh, Kl, Vh, Vl, 2, tid); CP_COMMIT();

    float o[2][8][4];
    #pragma unroll
    for (int mi = 0; mi < 2; ++mi)
        #pragma unroll
        for (int vi = 0; vi < 8; ++vi)
            #pragma unroll
            for (int q = 0; q < 4; ++q) o[mi][vi][q] = 0.0f;
    float mst[2][2] = {{-1e30f, -1e30f}, {-1e30f, -1e30f}};
    float lst[2][2] = {{0.0f, 0.0f}, {0.0f, 0.0f}};

    const int qrow = w * 32 + (lane & 15);
    const int qkoff = (lane >> 4) << 3;
    const int brow = lane & 7;
    const int bkoff = ((lane >> 3) & 1) << 3;
    const int vrow = (lane & 7) + bkoff;
    const int c0 = 2 * (lane & 3);
    const uint32_t losel = (lane & 16) ? F_KDL : 0;
    const int* msk = (const int*)(smf + F_MS);

    for (int t = 0; t < 32; ++t) {
        if (t < 30) { CP_WAIT(2); } else if (t == 30) { CP_WAIT(1); } else { CP_WAIT(0); }
        __syncthreads();
        const uint32_t st = sb + F_ST0 + (uint32_t)(t % 3) * F_STAGE;

        // S = Qs @ K^T  (32 rows x 64 keys per warp)
        float s[2][8][4];
        #pragma unroll
        for (int mi = 0; mi < 2; ++mi)
            #pragma unroll
            for (int ni = 0; ni < 8; ++ni)
                s[mi][ni][0] = s[mi][ni][1] = s[mi][ni][2] = s[mi][ni][3] = 0.0f;

        #pragma unroll
        for (int kc = 0; kc < 4; ++kc) {
            uint32_t qhf[2][4], qlf[2][4];
            #pragma unroll
            for (int mi = 0; mi < 2; ++mi) {
                const uint32_t ao = sb + (qrow + mi * 16) * 144 + (kc * 16 + qkoff) * 2;
                ldsm_x4(qhf[mi], ao);
                ldsm_x4(qlf[mi], ao + FQ_L);
            }
            #pragma unroll
            for (int ni = 0; ni < 8; ++ni) {
                uint32_t bb[4];
                const uint32_t bo = st + losel + (ni * 8 + brow) * 144 + (kc * 16 + bkoff) * 2;
                ldsm_x4(bb, bo);
                #pragma unroll
                for (int mi = 0; mi < 2; ++mi) {
                    mma16816(s[mi][ni], qhf[mi], bb);
                    mma16816(s[mi][ni], qhf[mi], bb + 2);
                    mma16816(s[mi][ni], qlf[mi], bb);
                }
            }
        }

        // mask
        #pragma unroll
        for (int ni = 0; ni < 8; ++ni) {
            const int m0 = msk[t * 64 + ni * 8 + c0];
            const int m1 = msk[t * 64 + ni * 8 + c0 + 1];
            if (m0 == 0) { s[0][ni][0] = s[0][ni][2] = s[1][ni][0] = s[1][ni][2] = -1e9f; }
            if (m1 == 0) { s[0][ni][1] = s[0][ni][3] = s[1][ni][1] = s[1][ni][3] = -1e9f; }
        }

        // online softmax (4 rows per lane: mi x rr)
        #pragma unroll
        for (int mi = 0; mi < 2; ++mi)
            #pragma unroll
            for (int rr = 0; rr < 2; ++rr) {
                float mx = -1e30f;
                #pragma unroll
                for (int ni = 0; ni < 8; ++ni)
                    mx = fmaxf(mx, fmaxf(s[mi][ni][rr * 2], s[mi][ni][rr * 2 + 1]));
                mx = fmaxf(mx, __shfl_xor_sync(0xffffffffu, mx, 1));
                mx = fmaxf(mx, __shfl_xor_sync(0xffffffffu, mx, 2));
                const float nm = fmaxf(mst[mi][rr], mx);
                const float corr = __expf(mst[mi][rr] - nm);
                float sum = 0.0f;
                #pragma unroll
                for (int ni = 0; ni < 8; ++ni) {
                    const float p0 = __expf(s[mi][ni][rr * 2]     - nm);
                    const float p1 = __expf(s[mi][ni][rr * 2 + 1] - nm);
                    s[mi][ni][rr * 2] = p0; s[mi][ni][rr * 2 + 1] = p1;
                    sum += p0 + p1;
                }
                sum += __shfl_xor_sync(0xffffffffu, sum, 1);
                sum += __shfl_xor_sync(0xffffffffu, sum, 2);
                lst[mi][rr] = lst[mi][rr] * corr + sum;
                mst[mi][rr] = nm;
                #pragma unroll
                for (int vi = 0; vi < 8; ++vi) {
                    o[mi][vi][rr * 2]     *= corr;
                    o[mi][vi][rr * 2 + 1] *= corr;
                }
            }

        // O += P @ V
        #pragma unroll
        for (int kc = 0; kc < 4; ++kc) {
            uint32_t ph[2][4], pl[2][4];
            #pragma unroll
            for (int mi = 0; mi < 2; ++mi) {
                bf16split2(s[mi][2 * kc][0],     s[mi][2 * kc][1],     ph[mi][0], pl[mi][0]);
                bf16split2(s[mi][2 * kc][2],     s[mi][2 * kc][3],     ph[mi][1], pl[mi][1]);
                bf16split2(s[mi][2 * kc + 1][0], s[mi][2 * kc + 1][1], ph[mi][2], pl[mi][2]);
                bf16split2(s[mi][2 * kc + 1][2], s[mi][2 * kc + 1][3], ph[mi][3], pl[mi][3]);
            }
            #pragma unroll
            for (int vi = 0; vi < 8; ++vi) {
                uint32_t vv[4];
                const uint32_t vo = st + F_VH + losel + (kc * 16 + vrow) * 144 + vi * 16;
                ldsm_x4t(vv, vo);
                #pragma unroll
                for (int mi = 0; mi < 2; ++mi) {
                    mma16816(o[mi][vi], ph[mi], vv);
                    mma16816(o[mi][vi], ph[mi], vv + 2);
                    mma16816(o[mi][vi], pl[mi], vv);
                }
            }
        }

        __syncthreads();
        if (t + 3 < 32) {
            kv_stage_issue(sb + F_ST0 + (uint32_t)(t % 3) * F_STAGE, Kh, Kl, Vh, Vl, t + 3, tid);
            CP_COMMIT();
        }
    }

    // epilogue: ctx bf16 hi/lo, flat [b*S+s][D] at col h*64+dk
    #pragma unroll
    for (int mi = 0; mi < 2; ++mi)
        #pragma unroll
        for (int rr = 0; rr < 2; ++rr) {
            const float inv = 1.0f / lst[mi][rr];
            const int r = q0 + w * 32 + mi * 16 + (lane >> 2) + rr * 8;
            const size_t base = ((size_t)b * S_N + r) * D_N + h * DK_N;
            #pragma unroll
            for (int vi = 0; vi < 8; ++vi) {
                const int dk = vi * 8 + c0;
                uint32_t hh, ll;
                bf16split2(o[mi][vi][rr * 2] * inv, o[mi][vi][rr * 2 + 1] * inv, hh, ll);
                *(uint32_t*)(g_ch + base + dk) = hh;
                *(uint32_t*)(g_cl + base + dk) = ll;
            }
        }
}

// ---------------------------------------------------------------------------
extern "C" void kernel_launch(void* const* d_in, const int* in_sizes, int n_in,
                              void* d_out, int out_size)
{
    (void)in_sizes; (void)n_in; (void)out_size;
    const float* query = (const float*)d_in[0];
    const float* key   = (const float*)d_in[1];
    const float* value = (const float*)d_in[2];
    const int*   mask  = (const int*)d_in[3];
    const float* Wq = (const float*)d_in[4];
    const float* bq = (const float*)d_in[5];
    const float* Wk = (const float*)d_in[6];
    const float* bk = (const float*)d_in[7];
    const float* Wv = (const float*)d_in[8];
    const float* bv = (const float*)d_in[9];
    const float* Wo = (const float*)d_in[10];
    const float* bo = (const float*)d_in[11];
    float* out = (float*)d_out;

    cudaFuncSetAttribute(qkv_proj_mma, cudaFuncAttributeMaxDynamicSharedMemorySize, SMEM_GEMM);
    cudaFuncSetAttribute(oproj_mma,    cudaFuncAttributeMaxDynamicSharedMemorySize, SMEM_GEMM);
    cudaFuncSetAttribute(flash_mma,    cudaFuncAttributeMaxDynamicSharedMemorySize, SMEM_FLASH);

    convert_in<<<dim3(HEAD_EL / 4 / 256, 1, 3), 256>>>(query, key, value);
    convert_w<<<dim3(1024 * 1024 / 4 / 256, 1, 4), 256>>>(Wq, Wk, Wv, Wo);

    // GEMM grid: N tiles (1024/256=4) x M tiles (8192/128=64) [x 3 for qkv]
    qkv_proj_mma<<<dim3(4, 64, 3), 256, SMEM_GEMM>>>(bq, bk, bv);

    flash_mma<<<dim3(S_N / 256, B_N * H_N), 256, SMEM_FLASH>>>(mask);

    oproj_mma<<<dim3(4, 64), 256, SMEM_GEMM>>>(bo, out);
}

// round 8
// speedup vs baseline: 1.0153x; 1.0153x over previous
#include <cuda_runtime.h>
#include <cuda_bf16.h>
#include <stdint.h>

// Problem constants
#define B_N 4
#define S_N 2048
#define D_N 1024
#define H_N 16
#define DK_N 64

#define HEAD_EL (8192u * 1024u)        // B*H*S*DK == M*D
#define IN_EL   (3u * HEAD_EL)
#define W_EL    (4u * 1024u * 1024u)

// bf16 hi/lo scratch (allocation-free: static device globals)
__device__ __nv_bfloat16 g_inh[IN_EL], g_inl[IN_EL];
__device__ __nv_bfloat16 g_wh[W_EL],  g_wl[W_EL];
__device__ __nv_bfloat16 g_qh[HEAD_EL], g_ql[HEAD_EL];
__device__ __nv_bfloat16 g_kh[HEAD_EL], g_kl[HEAD_EL];
__device__ __nv_bfloat16 g_vh[HEAD_EL], g_vl[HEAD_EL];
__device__ __nv_bfloat16 g_ch[HEAD_EL], g_cl[HEAD_EL];

// ===========================================================================
// Helpers (compute_103-portable: ldmatrix / mma.sync / cp.async)
// ===========================================================================
__device__ __forceinline__ uint32_t smem_u32(const void* p) {
    uint32_t a;
    asm("{ .reg .u64 t; cvta.to.shared.u64 t, %1; cvt.u32.u64 %0, t; }"
        : "=r"(a) : "l"(p));
    return a;
}
__device__ __forceinline__ void ldsm_x4(uint32_t* r, uint32_t addr) {
    asm volatile("ldmatrix.sync.aligned.m8n8.x4.shared.b16 {%0,%1,%2,%3}, [%4];"
        : "=r"(r[0]), "=r"(r[1]), "=r"(r[2]), "=r"(r[3]) : "r"(addr));
}
__device__ __forceinline__ void ldsm_x4t(uint32_t* r, uint32_t addr) {
    asm volatile("ldmatrix.sync.aligned.m8n8.x4.trans.shared.b16 {%0,%1,%2,%3}, [%4];"
        : "=r"(r[0]), "=r"(r[1]), "=r"(r[2]), "=r"(r[3]) : "r"(addr));
}
__device__ __forceinline__ void mma16816(float* d, const uint32_t* a, const uint32_t* b) {
    asm volatile(
        "mma.sync.aligned.m16n8k16.row.col.f32.bf16.bf16.f32 "
        "{%0,%1,%2,%3}, {%4,%5,%6,%7}, {%8,%9}, {%0,%1,%2,%3};"
        : "+f"(d[0]), "+f"(d[1]), "+f"(d[2]), "+f"(d[3])
        : "r"(a[0]), "r"(a[1]), "r"(a[2]), "r"(a[3]), "r"(b[0]), "r"(b[1]));
}
__device__ __forceinline__ void bf16split2(float x, float y, uint32_t& hi, uint32_t& lo) {
    union { __nv_bfloat162 b; uint32_t u; } h, l;
    h.b = __floats2bfloat162_rn(x, y);
    l.b = __floats2bfloat162_rn(x - __low2float(h.b), y - __high2float(h.b));
    hi = h.u; lo = l.u;
}
__device__ __forceinline__ void cpa16(uint32_t s, const void* g) {
    asm volatile("cp.async.cg.shared.global [%0], [%1], 16;" :: "r"(s), "l"(g));
}
#define CP_COMMIT() asm volatile("cp.async.commit_group;" ::: "memory")
#define CP_WAIT(n)  asm volatile("cp.async.wait_group %0;" :: "n"(n) : "memory")

// ===========================================================================
// Pre-pass: fp32 -> bf16 hi/lo (fused: 3 inputs / 4 weights per launch)
// ===========================================================================
__global__ __launch_bounds__(256) void convert_in(
    const float* __restrict__ q, const float* __restrict__ k,
    const float* __restrict__ v)
{
    const int z = blockIdx.z;
    const float* src = (z == 0) ? q : (z == 1) ? k : v;
    __nv_bfloat16* dh = g_inh + (size_t)z * HEAD_EL;
    __nv_bfloat16* dl = g_inl + (size_t)z * HEAD_EL;
    const int i = blockIdx.x * 256 + threadIdx.x;
    const float4 val = ((const float4*)src)[i];
    uint32_t h0, l0, h1, l1;
    bf16split2(val.x, val.y, h0, l0);
    bf16split2(val.z, val.w, h1, l1);
    ((uint2*)dh)[i] = make_uint2(h0, h1);
    ((uint2*)dl)[i] = make_uint2(l0, l1);
}

__global__ __launch_bounds__(256) void convert_w(
    const float* __restrict__ wq, const float* __restrict__ wk,
    const float* __restrict__ wv, const float* __restrict__ wo)
{
    const int z = blockIdx.z;
    const float* src = (z == 0) ? wq : (z == 1) ? wk : (z == 2) ? wv : wo;
    __nv_bfloat16* dh = g_wh + (size_t)z * 1024 * 1024;
    __nv_bfloat16* dl = g_wl + (size_t)z * 1024 * 1024;
    const int i = blockIdx.x * 256 + threadIdx.x;
    const float4 val = ((const float4*)src)[i];
    uint32_t h0, l0, h1, l1;
    bf16split2(val.x, val.y, h0, l0);
    bf16split2(val.z, val.w, h1, l1);
    ((uint2*)dh)[i] = make_uint2(h0, h1);
    ((uint2*)dl)[i] = make_uint2(l0, l1);
}

// ===========================================================================
// GEMM: D = A @ W^T (+bias). CTA 256(M) x 128(N), BK=32, 512 thr
// (16 warps: 8m x 2n, warp tile 32x64), 3-stage cp.async pipeline.
// Stage: Ah(20480) Al(20480) Bh(10240) Bl(10240) = 61440 B. Row stride 80 B.
// ===========================================================================
#define G_AH 0
#define G_AL 20480
#define G_BH 40960
#define G_BDL 10240             // Bl - Bh
#define G_STAGE 61440
#define SMEM_GEMM (3 * G_STAGE)

__device__ __forceinline__ void gemm_stage_issue(
    uint32_t st, const __nv_bfloat16* __restrict__ Ah,
    const __nv_bfloat16* __restrict__ Al, const __nv_bfloat16* __restrict__ Wh,
    const __nv_bfloat16* __restrict__ Wl, int kt, int tid)
{
    #pragma unroll
    for (int i = 0; i < 2; ++i) {         // A: 256 rows x 4 chunks, hi+lo
        const int c = tid + i * 512;
        const int row = c >> 2, ch = c & 3;
        const uint32_t d = st + row * 80 + ch * 16;
        const size_t s = (size_t)row * 1024 + kt * 32 + ch * 8;
        cpa16(d + G_AH, Ah + s);
        cpa16(d + G_AL, Al + s);
    }
    {                                      // B: 128 rows x 4 chunks, hi+lo
        const int c = tid;                 // 0..511
        const int row = c >> 2, ch = c & 3;
        const uint32_t d = st + G_BH + row * 80 + ch * 16;
        const size_t s = (size_t)row * 1024 + kt * 32 + ch * 8;
        cpa16(d, Wh + s);
        cpa16(d + G_BDL, Wl + s);
    }
}

template <int MODE>
__device__ __forceinline__ void gemm_bf_body(
    const __nv_bfloat16* __restrict__ Ah, const __nv_bfloat16* __restrict__ Al,
    const __nv_bfloat16* __restrict__ Wh, const __nv_bfloat16* __restrict__ Wl,
    const float* __restrict__ bias, float scale,
    float* __restrict__ outf,
    __nv_bfloat16* __restrict__ outh, __nv_bfloat16* __restrict__ outl,
    int bm, int bn)
{
    extern __shared__ char smg[];
    const uint32_t sb = smem_u32(smg);
    const int tid = threadIdx.x;
    const int lane = tid & 31;
    const int w = tid >> 5;
    const int wm = w & 7;               // 0..7 -> rows wm*32
    const int wn = w >> 3;              // 0..1 -> cols wn*64

    const __nv_bfloat16* Agh = Ah + (size_t)bm * 256 * 1024;
    const __nv_bfloat16* Agl = Al + (size_t)bm * 256 * 1024;
    const __nv_bfloat16* Wgh = Wh + (size_t)bn * 128 * 1024;
    const __nv_bfloat16* Wgl = Wl + (size_t)bn * 128 * 1024;

    gemm_stage_issue(sb,               Agh, Agl, Wgh, Wgl, 0, tid); CP_COMMIT();
    gemm_stage_issue(sb + G_STAGE,     Agh, Agl, Wgh, Wgl, 1, tid); CP_COMMIT();
    gemm_stage_issue(sb + 2 * G_STAGE, Agh, Agl, Wgh, Wgl, 2, tid); CP_COMMIT();

    float d[2][8][4];
    #pragma unroll
    for (int mi = 0; mi < 2; ++mi)
        #pragma unroll
        for (int ni = 0; ni < 8; ++ni)
            #pragma unroll
            for (int q = 0; q < 4; ++q) d[mi][ni][q] = 0.0f;

    const int arow = wm * 32 + (lane & 15);
    const int akoff = (lane >> 4) << 3;
    const int brow = wn * 64 + (lane & 7);
    const int bkoff = ((lane >> 3) & 1) << 3;
    const uint32_t losel = (lane & 16) ? G_BDL : 0;

    for (int kt = 0; kt < 32; ++kt) {
        if (kt < 30) { CP_WAIT(2); } else if (kt == 30) { CP_WAIT(1); } else { CP_WAIT(0); }
        __syncthreads();
        const uint32_t st = sb + (uint32_t)(kt % 3) * G_STAGE;
        #pragma unroll
        for (int kk = 0; kk < 32; kk += 16) {
            uint32_t ah[2][4], al[2][4];
            #pragma unroll
            for (int mi = 0; mi < 2; ++mi) {
                const uint32_t ao = st + (arow + mi * 16) * 80 + (kk + akoff) * 2;
                ldsm_x4(ah[mi], ao + G_AH);
                ldsm_x4(al[mi], ao + G_AL);
            }
            #pragma unroll
            for (int ni = 0; ni < 8; ++ni) {
                uint32_t bb[4];   // [0..1]=hi, [2..3]=lo (combined x4)
                const uint32_t bo = st + G_BH + losel + (brow + ni * 8) * 80 + (kk + bkoff) * 2;
                ldsm_x4(bb, bo);
                #pragma unroll
                for (int mi = 0; mi < 2; ++mi) {
                    mma16816(d[mi][ni], ah[mi], bb);
                    mma16816(d[mi][ni], ah[mi], bb + 2);
                    mma16816(d[mi][ni], al[mi], bb);
                }
            }
        }
        __syncthreads();
        if (kt + 3 < 32) {
            gemm_stage_issue(sb + (uint32_t)(kt % 3) * G_STAGE, Agh, Agl, Wgh, Wgl, kt + 3, tid);
            CP_COMMIT();
        }
    }

    // epilogue
    const int r_base = bm * 256 + wm * 32 + (lane >> 2);
    const int c_base = bn * 128 + wn * 64 + 2 * (lane & 3);
    #pragma unroll
    for (int mi = 0; mi < 2; ++mi)
        #pragma unroll
        for (int ni = 0; ni < 8; ++ni) {
            const int col = c_base + ni * 8;
            const float b0 = bias[col], b1 = bias[col + 1];
            #pragma unroll
            for (int rr = 0; rr < 2; ++rr) {
                const int row = r_base + mi * 16 + rr * 8;
                const float vx = (d[mi][ni][rr * 2 + 0] + b0) * scale;
                const float vy = (d[mi][ni][rr * 2 + 1] + b1) * scale;
                if (MODE == 1) {
                    const int bb = row >> 11;
                    const int s = row & (S_N - 1);
                    const int hh = col >> 6;
                    const int dk = col & 63;
                    const size_t idx = (((size_t)(bb * H_N + hh) * S_N + s) * DK_N) + dk;
                    uint32_t h, l;
                    bf16split2(vx, vy, h, l);
                    *(uint32_t*)(outh + idx) = h;
                    *(uint32_t*)(outl + idx) = l;
                } else {
                    float2 v; v.x = vx; v.y = vy;
                    *(float2*)(outf + (size_t)row * D_N + col) = v;
                }
            }
        }
}

__global__ __launch_bounds__(512, 1) void qkv_proj_mma(
    const float* __restrict__ bq, const float* __restrict__ bk,
    const float* __restrict__ bv)
{
    const int z = blockIdx.z;
    const float* bias = (z == 0) ? bq : (z == 1) ? bk : bv;
    __nv_bfloat16* oh = (z == 0) ? g_qh : (z == 1) ? g_kh : g_vh;
    __nv_bfloat16* ol = (z == 0) ? g_ql : (z == 1) ? g_kl : g_vl;
    const float scale = (z == 0) ? 0.125f : 1.0f;
    gemm_bf_body<1>(g_inh + (size_t)z * HEAD_EL, g_inl + (size_t)z * HEAD_EL,
                    g_wh + (size_t)z * 1024 * 1024, g_wl + (size_t)z * 1024 * 1024,
                    bias, scale, nullptr, oh, ol, blockIdx.y, blockIdx.x);
}

__global__ __launch_bounds__(512, 1) void oproj_mma(
    const float* __restrict__ bo, float* __restrict__ out)
{
    gemm_bf_body<0>(g_ch, g_cl,
                    g_wh + (size_t)3 * 1024 * 1024, g_wl + (size_t)3 * 1024 * 1024,
                    bo, 1.0f, out, nullptr, nullptr, blockIdx.y, blockIdx.x);
}

// ===========================================================================
// Flash attention: CTA = one (b,h) x 256 q-rows, 512 thr (16 warps x 16 rows),
// 64-key tiles, 2-stage cp.async KV pipeline, online softmax.
// Q persistent in smem (hi/lo, re-LDSM per k-chunk -> low regs).
// Stage: Kh(9216) Kl(9216) Vh(9216) Vl(9216) = 36864 B. Row stride 144 B.
// ===========================================================================
#define FQ_L 36864               // Q lo offset (Q comp = 256*144)
#define F_ST0 73728
#define F_KDL 9216               // Kl-Kh / Vl-Vh
#define F_VH 18432
#define F_STAGE 36864
#define F_MS (F_ST0 + 2 * F_STAGE)     // 147456
#define SMEM_FLASH (F_MS + 8192)       // 155648

__device__ __forceinline__ void kv_stage_issue(
    uint32_t st, const __nv_bfloat16* __restrict__ kh,
    const __nv_bfloat16* __restrict__ kl, const __nv_bfloat16* __restrict__ vh,
    const __nv_bfloat16* __restrict__ vl, int t, int tid)
{
    #pragma unroll
    for (int comp = 0; comp < 4; ++comp) {
        const int c = tid & 511;                // 0..511
        const int row = c >> 3, ch = c & 7;
        const uint32_t d = st + comp * 9216 + row * 144 + ch * 16;
        const __nv_bfloat16* src =
            (comp == 0 ? kh : comp == 1 ? kl : comp == 2 ? vh : vl)
            + ((size_t)t * 64 + row) * 64 + ch * 8;
        cpa16(d, src);
    }
}

__global__ __launch_bounds__(512, 1)
void flash_mma(const int* __restrict__ mask)
{
    extern __shared__ char smf[];
    const uint32_t sb = smem_u32(smf);
    const int tid = threadIdx.x;
    const int lane = tid & 31;
    const int w = tid >> 5;
    const int bh = blockIdx.y;
    const int q0 = blockIdx.x * 256;
    const int b = bh >> 4;
    const int h = bh & 15;

    const size_t hoff = (size_t)bh * S_N * DK_N;
    const __nv_bfloat16* Qh = g_qh + hoff + (size_t)q0 * DK_N;
    const __nv_bfloat16* Ql = g_ql + hoff + (size_t)q0 * DK_N;
    const __nv_bfloat16* Kh = g_kh + hoff;
    const __nv_bfloat16* Kl = g_kl + hoff;
    const __nv_bfloat16* Vh = g_vh + hoff;
    const __nv_bfloat16* Vl = g_vl + hoff;
    const int* mg = mask + b * S_N;

    // prologue: Q (hi/lo) + mask (group 0), KV stages 0,1 (groups 1,2)
    #pragma unroll
    for (int i = 0; i < 4; ++i) {
        const int c = tid + i * 512;            // 0..2047
        const int row = c >> 3, ch = c & 7;
        const uint32_t d = sb + row * 144 + ch * 16;
        const size_t s = (size_t)row * 64 + ch * 8;
        cpa16(d, Qh + s);
        cpa16(d + FQ_L, Ql + s);
    }
    cpa16(sb + F_MS + tid * 16, mg + tid * 4);  // 512 chunks = 8192 B
    CP_COMMIT();
    kv_stage_issue(sb + F_ST0,           Kh, Kl, Vh, Vl, 0, tid); CP_COMMIT();
    kv_stage_issue(sb + F_ST0 + F_STAGE, Kh, Kl, Vh, Vl, 1, tid); CP_COMMIT();

    float o[8][4];
    #pragma unroll
    for (int vi = 0; vi < 8; ++vi)
        #pragma unroll
        for (int q = 0; q < 4; ++q) o[vi][q] = 0.0f;
    float mst[2] = {-1e30f, -1e30f};
    float lst[2] = {0.0f, 0.0f};

    const int qrow = w * 16 + (lane & 15);
    const int qkoff = (lane >> 4) << 3;
    const int brow = lane & 7;
    const int bkoff = ((lane >> 3) & 1) << 3;
    const int vrow = (lane & 7) + bkoff;
    const int c0 = 2 * (lane & 3);
    const uint32_t losel = (lane & 16) ? F_KDL : 0;
    const int* msk = (const int*)(smf + F_MS);

    for (int t = 0; t < 32; ++t) {
        if (t < 31) { CP_WAIT(1); } else { CP_WAIT(0); }
        __syncthreads();
        const uint32_t st = sb + F_ST0 + (uint32_t)(t & 1) * F_STAGE;

        // S = Qs @ K^T  (16 rows x 64 keys per warp)
        float s[8][4];
        #pragma unroll
        for (int ni = 0; ni < 8; ++ni)
            s[ni][0] = s[ni][1] = s[ni][2] = s[ni][3] = 0.0f;

        #pragma unroll
        for (int kc = 0; kc < 4; ++kc) {
            uint32_t qhf[4], qlf[4];
            const uint32_t ao = sb + qrow * 144 + (kc * 16 + qkoff) * 2;
            ldsm_x4(qhf, ao);
            ldsm_x4(qlf, ao + FQ_L);
            #pragma unroll
            for (int ni = 0; ni < 8; ++ni) {
                uint32_t bb[4];
                const uint32_t bo = st + losel + (ni * 8 + brow) * 144 + (kc * 16 + bkoff) * 2;
                ldsm_x4(bb, bo);
                mma16816(s[ni], qhf, bb);
                mma16816(s[ni], qhf, bb + 2);
                mma16816(s[ni], qlf, bb);
            }
        }

        // mask
        #pragma unroll
        for (int ni = 0; ni < 8; ++ni) {
            if (msk[t * 64 + ni * 8 + c0] == 0)     { s[ni][0] = -1e9f; s[ni][2] = -1e9f; }
            if (msk[t * 64 + ni * 8 + c0 + 1] == 0) { s[ni][1] = -1e9f; s[ni][3] = -1e9f; }
        }

        // online softmax (2 rows per lane)
        #pragma unroll
        for (int rr = 0; rr < 2; ++rr) {
            float mx = -1e30f;
            #pragma unroll
            for (int ni = 0; ni < 8; ++ni)
                mx = fmaxf(mx, fmaxf(s[ni][rr * 2], s[ni][rr * 2 + 1]));
            mx = fmaxf(mx, __shfl_xor_sync(0xffffffffu, mx, 1));
            mx = fmaxf(mx, __shfl_xor_sync(0xffffffffu, mx, 2));
            const float nm = fmaxf(mst[rr], mx);
            const float corr = __expf(mst[rr] - nm);
            float sum = 0.0f;
            #pragma unroll
            for (int ni = 0; ni < 8; ++ni) {
                const float p0 = __expf(s[ni][rr * 2]     - nm);
                const float p1 = __expf(s[ni][rr * 2 + 1] - nm);
                s[ni][rr * 2] = p0; s[ni][rr * 2 + 1] = p1;
                sum += p0 + p1;
            }
            sum += __shfl_xor_sync(0xffffffffu, sum, 1);
            sum += __shfl_xor_sync(0xffffffffu, sum, 2);
            lst[rr] = lst[rr] * corr + sum;
            mst[rr] = nm;
            #pragma unroll
            for (int vi = 0; vi < 8; ++vi) {
                o[vi][rr * 2]     *= corr;
                o[vi][rr * 2 + 1] *= corr;
            }
        }

        // O += P @ V
        #pragma unroll
        for (int kc = 0; kc < 4; ++kc) {
            uint32_t ph[4], pl[4];
            bf16split2(s[2 * kc][0],     s[2 * kc][1],     ph[0], pl[0]);
            bf16split2(s[2 * kc][2],     s[2 * kc][3],     ph[1], pl[1]);
            bf16split2(s[2 * kc + 1][0], s[2 * kc + 1][1], ph[2], pl[2]);
            bf16split2(s[2 * kc + 1][2], s[2 * kc + 1][3], ph[3], pl[3]);
            #pragma unroll
            for (int vi = 0; vi < 8; ++vi) {
                uint32_t vv[4];
                const uint32_t vo = st + F_VH + losel + (kc * 16 + vrow) * 144 + vi * 16;
                ldsm_x4t(vv, vo);
                mma16816(o[vi], ph, vv);
                mma16816(o[vi], ph, vv + 2);
                mma16816(o[vi], pl, vv);
            }
        }

        __syncthreads();
        if (t + 2 < 32) {
            kv_stage_issue(sb + F_ST0 + (uint32_t)(t & 1) * F_STAGE, Kh, Kl, Vh, Vl, t + 2, tid);
            CP_COMMIT();
        }
    }

    // epilogue: ctx bf16 hi/lo, flat [b*S+s][D] at col h*64+dk
    #pragma unroll
    for (int rr = 0; rr < 2; ++rr) {
        const float inv = 1.0f / lst[rr];
        const int r = q0 + w * 16 + (lane >> 2) + rr * 8;
        const size_t base = ((size_t)b * S_N + r) * D_N + h * DK_N;
        #pragma unroll
        for (int vi = 0; vi < 8; ++vi) {
            const int dk = vi * 8 + c0;
            uint32_t hh, ll;
            bf16split2(o[vi][rr * 2] * inv, o[vi][rr * 2 + 1] * inv, hh, ll);
            *(uint32_t*)(g_ch + base + dk) = hh;
            *(uint32_t*)(g_cl + base + dk) = ll;
        }
    }
}

// ---------------------------------------------------------------------------
extern "C" void kernel_launch(void* const* d_in, const int* in_sizes, int n_in,
                              void* d_out, int out_size)
{
    (void)in_sizes; (void)n_in; (void)out_size;
    const float* query = (const float*)d_in[0];
    const float* key   = (const float*)d_in[1];
    const float* value = (const float*)d_in[2];
    const int*   mask  = (const int*)d_in[3];
    const float* Wq = (const float*)d_in[4];
    const float* bq = (const float*)d_in[5];
    const float* Wk = (const float*)d_in[6];
    const float* bk = (const float*)d_in[7];
    const float* Wv = (const float*)d_in[8];
    const float* bv = (const float*)d_in[9];
    const float* Wo = (const float*)d_in[10];
    const float* bo = (const float*)d_in[11];
    float* out = (float*)d_out;

    cudaFuncSetAttribute(qkv_proj_mma, cudaFuncAttributeMaxDynamicSharedMemorySize, SMEM_GEMM);
    cudaFuncSetAttribute(oproj_mma,    cudaFuncAttributeMaxDynamicSharedMemorySize, SMEM_GEMM);
    cudaFuncSetAttribute(flash_mma,    cudaFuncAttributeMaxDynamicSharedMemorySize, SMEM_FLASH);

    convert_in<<<dim3(HEAD_EL / 4 / 256, 1, 3), 256>>>(query, key, value);
    convert_w<<<dim3(1024 * 1024 / 4 / 256, 1, 4), 256>>>(Wq, Wk, Wv, Wo);

    // GEMM grid: N tiles (1024/128=8) x M tiles (8192/256=32) [x3 for qkv]
    qkv_proj_mma<<<dim3(8, 32, 3), 512, SMEM_GEMM>>>(bq, bk, bv);

    flash_mma<<<dim3(S_N / 256, B_N * H_N), 512, SMEM_FLASH>>>(mask);

    oproj_mma<<<dim3(8, 32), 512, SMEM_GEMM>>>(bo, out);
}